// round 1
// baseline (speedup 1.0000x reference)
#include <cuda_runtime.h>
#include <math.h>

#define B   64
#define C   256
#define HW  4096
#define CS  64
#define NC  8
#define BC  (B*C)          // 16384
#define Q_MAX 255.0f
#define SMOOTH 0.995f

// ---- scratch (no allocations allowed) ----
__device__ float g_pooled[BC];
__device__ float g_xmin[BC];
__device__ float g_xmax[BC];
__device__ float g_scale[BC];
__device__ float g_smin[B];
__device__ float g_smax[B];
__device__ float g_ss[B];
__device__ float g_zz[B];
__device__ float g_is[B];

// ============ K1: per-(b,c) sum / min / max over HW=4096 ============
__global__ void __launch_bounds__(256) k1_stats(const float* __restrict__ x) {
    const int bc  = blockIdx.x;             // 0..16383
    const int tid = threadIdx.x;
    const float4* xb = reinterpret_cast<const float4*>(x) + (size_t)bc * (HW/4);

    float sum = 0.f, mn = INFINITY, mx = -INFINITY;
#pragma unroll
    for (int i = 0; i < 4; i++) {
        float4 v = xb[tid + i*256];
        sum += (v.x + v.y) + (v.z + v.w);
        mn = fminf(mn, fminf(fminf(v.x, v.y), fminf(v.z, v.w)));
        mx = fmaxf(mx, fmaxf(fmaxf(v.x, v.y), fmaxf(v.z, v.w)));
    }
    // warp reduce
#pragma unroll
    for (int o = 16; o > 0; o >>= 1) {
        sum += __shfl_xor_sync(0xFFFFFFFFu, sum, o);
        mn = fminf(mn, __shfl_xor_sync(0xFFFFFFFFu, mn, o));
        mx = fmaxf(mx, __shfl_xor_sync(0xFFFFFFFFu, mx, o));
    }
    __shared__ float ssum[8], smn[8], smx[8];
    const int wid = tid >> 5, lid = tid & 31;
    if (lid == 0) { ssum[wid] = sum; smn[wid] = mn; smx[wid] = mx; }
    __syncthreads();
    if (tid == 0) {
        float ts = 0.f, tn = INFINITY, tx = -INFINITY;
#pragma unroll
        for (int w = 0; w < 8; w++) {
            ts += ssum[w]; tn = fminf(tn, smn[w]); tx = fmaxf(tx, smx[w]);
        }
        g_pooled[bc] = ts * (1.0f / HW);
        g_xmin[bc] = tn;
        g_xmax[bc] = tx;
    }
}

// ============ K2: SE MLP per sample b (one block/sample) ============
__global__ void __launch_bounds__(256) k2_se(const float* __restrict__ w1,
                                             const float* __restrict__ b1,
                                             const float* __restrict__ w2,
                                             const float* __restrict__ b2) {
    const int b = blockIdx.x;
    const int tid = threadIdx.x;
    __shared__ float sp[C];     // pooled[b, :]
    __shared__ float sh[CS];    // hidden
    __shared__ float rmn[8], rmx[8];

    sp[tid] = g_pooled[b*C + tid];
    __syncthreads();

    if (tid < CS) {
        float acc = b1[tid];
        const float* wr = w1 + tid * C;
#pragma unroll 4
        for (int c = 0; c < C; c++) acc = fmaf(sp[c], wr[c], acc);
        sh[tid] = fmaxf(acc, 0.f);   // relu
    }
    __syncthreads();

    // v[c] and scale[c], c = tid
    {
        float acc = b2[tid];
        const float* wr = w2 + tid * CS;
#pragma unroll 4
        for (int s = 0; s < CS; s++) acc = fmaf(sh[s], wr[s], acc);
        float sc = fminf(fmaxf(acc * (1.0f/6.0f) + 0.5f, 0.f), 1.f);  // hardsigmoid
        const int idx = b*C + tid;
        g_scale[idx] = sc;
        // per-sample min/max candidates (scale >= 0 so min/max commute with mult)
        float lmn = sc * g_xmin[idx];
        float lmx = sc * g_xmax[idx];
#pragma unroll
        for (int o = 16; o > 0; o >>= 1) {
            lmn = fminf(lmn, __shfl_xor_sync(0xFFFFFFFFu, lmn, o));
            lmx = fmaxf(lmx, __shfl_xor_sync(0xFFFFFFFFu, lmx, o));
        }
        const int wid = tid >> 5, lid = tid & 31;
        if (lid == 0) { rmn[wid] = lmn; rmx[wid] = lmx; }
    }
    __syncthreads();
    if (tid == 0) {
        float tn = INFINITY, tx = -INFINITY;
#pragma unroll
        for (int w = 0; w < 8; w++) { tn = fminf(tn, rmn[w]); tx = fmaxf(tx, rmx[w]); }
        g_smin[b] = tn;
        g_smax[b] = tx;
    }
}

// ============ K3: cluster EMA + quant params (1 block, 64 threads) ============
__global__ void __launch_bounds__(64) k3_quant(const float* __restrict__ act_range,
                                               const int*   __restrict__ sc) {
    const int tid = threadIdx.x;
    __shared__ float cs_s[NC], cs_z[NC];
    if (tid < NC) {
        float mn = INFINITY, mx = -INFINITY;
        for (int b = 0; b < B; b++) {
            if (sc[b] == tid) {
                mn = fminf(mn, g_smin[b]);
                mx = fmaxf(mx, g_smax[b]);
            }
        }
        float nmin = act_range[tid*2 + 0] * SMOOTH + mn * (1.0f - SMOOTH);
        float nmax = act_range[tid*2 + 1] * SMOOTH + mx * (1.0f - SMOOTH);
        float s = (nmax - nmin) * (1.0f / Q_MAX);
        float z = -rintf(nmin / s);
        cs_s[tid] = s;
        cs_z[tid] = z;
    }
    __syncthreads();
    {
        const int k = sc[tid];
        float s = cs_s[k];
        g_ss[tid] = s;
        g_zz[tid] = cs_z[k];
        g_is[tid] = 1.0f / s;
    }
}

// ============ K4: elementwise fake-quant, float4 ============
__global__ void __launch_bounds__(256) k4_fq(const float* __restrict__ x,
                                             float* __restrict__ out) {
    // blockDim=256, 1024 float4 per (b,c) => bc uniform per block
    const int gid = blockIdx.x * 256 + threadIdx.x;
    const int bc  = blockIdx.x >> 2;
    const int b   = bc >> 8;
    const float sc = g_scale[bc];
    const float s_ = g_ss[b], z_ = g_zz[b], is_ = g_is[b];

    float4 v = reinterpret_cast<const float4*>(x)[gid];
    float4 r;
    {
        float o, q;
        o = sc * v.x; q = fminf(fmaxf(rintf(fmaf(o, is_, z_)), 0.f), Q_MAX); r.x = (q - z_) * s_;
        o = sc * v.y; q = fminf(fmaxf(rintf(fmaf(o, is_, z_)), 0.f), Q_MAX); r.y = (q - z_) * s_;
        o = sc * v.z; q = fminf(fmaxf(rintf(fmaf(o, is_, z_)), 0.f), Q_MAX); r.z = (q - z_) * s_;
        o = sc * v.w; q = fminf(fmaxf(rintf(fmaf(o, is_, z_)), 0.f), Q_MAX); r.w = (q - z_) * s_;
    }
    reinterpret_cast<float4*>(out)[gid] = r;
}

extern "C" void kernel_launch(void* const* d_in, const int* in_sizes, int n_in,
                              void* d_out, int out_size) {
    const float* x   = (const float*)d_in[0];
    const float* w1  = (const float*)d_in[1];
    const float* b1  = (const float*)d_in[2];
    const float* w2  = (const float*)d_in[3];
    const float* b2  = (const float*)d_in[4];
    const float* ar  = (const float*)d_in[5];
    const int*   sc  = (const int*)  d_in[6];
    float* out = (float*)d_out;

    k1_stats<<<BC, 256>>>(x);
    k2_se<<<B, 256>>>(w1, b1, w2, b2);
    k3_quant<<<1, 64>>>(ar, sc);
    k4_fq<<<(B*C*HW)/(4*256), 256>>>(x, out);
}

// round 2
// speedup vs baseline: 1.2528x; 1.2528x over previous
#include <cuda_runtime.h>
#include <math.h>

#define B   64
#define C   256
#define HW  4096
#define CS  64
#define NC  8
#define BC  (B*C)          // 16384
#define Q_MAX 255.0f
#define SMOOTH 0.995f

// ---- scratch (no allocations allowed) ----
__device__ float g_pooled[BC];
__device__ float g_xmin[BC];
__device__ float g_xmax[BC];
__device__ float g_scale[BC];
__device__ float g_smin[B];
__device__ float g_smax[B];
__device__ float g_ss[B];
__device__ float g_zz[B];
__device__ float g_is[B];

// ============ K1: per-(b,c) sum / min / max over HW=4096 ============
// Forward bc order: leaves the TAIL of x resident in L2 for K4 (reverse order).
__global__ void __launch_bounds__(256) k1_stats(const float* __restrict__ x) {
    const int bc  = blockIdx.x;             // 0..16383
    const int tid = threadIdx.x;
    const float4* xb = reinterpret_cast<const float4*>(x) + (size_t)bc * (HW/4);

    float4 v0 = xb[tid];
    float4 v1 = xb[tid + 256];
    float4 v2 = xb[tid + 512];
    float4 v3 = xb[tid + 768];

    float sum = ((v0.x + v0.y) + (v0.z + v0.w)) + ((v1.x + v1.y) + (v1.z + v1.w))
              + ((v2.x + v2.y) + (v2.z + v2.w)) + ((v3.x + v3.y) + (v3.z + v3.w));
    float mn = fminf(fminf(fminf(fminf(v0.x, v0.y), fminf(v0.z, v0.w)),
                           fminf(fminf(v1.x, v1.y), fminf(v1.z, v1.w))),
                     fminf(fminf(fminf(v2.x, v2.y), fminf(v2.z, v2.w)),
                           fminf(fminf(v3.x, v3.y), fminf(v3.z, v3.w))));
    float mx = fmaxf(fmaxf(fmaxf(fmaxf(v0.x, v0.y), fmaxf(v0.z, v0.w)),
                           fmaxf(fmaxf(v1.x, v1.y), fmaxf(v1.z, v1.w))),
                     fmaxf(fmaxf(fmaxf(v2.x, v2.y), fmaxf(v2.z, v2.w)),
                           fmaxf(fmaxf(v3.x, v3.y), fmaxf(v3.z, v3.w))));
    // warp reduce
#pragma unroll
    for (int o = 16; o > 0; o >>= 1) {
        sum += __shfl_xor_sync(0xFFFFFFFFu, sum, o);
        mn = fminf(mn, __shfl_xor_sync(0xFFFFFFFFu, mn, o));
        mx = fmaxf(mx, __shfl_xor_sync(0xFFFFFFFFu, mx, o));
    }
    __shared__ float ssum[8], smn[8], smx[8];
    const int wid = tid >> 5, lid = tid & 31;
    if (lid == 0) { ssum[wid] = sum; smn[wid] = mn; smx[wid] = mx; }
    __syncthreads();
    if (tid == 0) {
        float ts = 0.f, tn = INFINITY, tx = -INFINITY;
#pragma unroll
        for (int w = 0; w < 8; w++) {
            ts += ssum[w]; tn = fminf(tn, smn[w]); tx = fmaxf(tx, smx[w]);
        }
        g_pooled[bc] = ts * (1.0f / HW);
        g_xmin[bc] = tn;
        g_xmax[bc] = tx;
    }
}

// ============ K2: SE MLP per sample b (one block/sample) ============
__global__ void __launch_bounds__(256) k2_se(const float* __restrict__ w1,
                                             const float* __restrict__ b1,
                                             const float* __restrict__ w2,
                                             const float* __restrict__ b2) {
    const int b = blockIdx.x;
    const int tid = threadIdx.x;
    __shared__ float sp[C];     // pooled[b, :]
    __shared__ float sh[CS];    // hidden
    __shared__ float rmn[8], rmx[8];

    sp[tid] = g_pooled[b*C + tid];
    __syncthreads();

    if (tid < CS) {
        float acc = b1[tid];
        const float* wr = w1 + tid * C;
#pragma unroll 4
        for (int c = 0; c < C; c++) acc = fmaf(sp[c], wr[c], acc);
        sh[tid] = fmaxf(acc, 0.f);   // relu
    }
    __syncthreads();

    // v[c] and scale[c], c = tid
    {
        float acc = b2[tid];
        const float* wr = w2 + tid * CS;
#pragma unroll 4
        for (int s = 0; s < CS; s++) acc = fmaf(sh[s], wr[s], acc);
        float sc = fminf(fmaxf(acc * (1.0f/6.0f) + 0.5f, 0.f), 1.f);  // hardsigmoid
        const int idx = b*C + tid;
        g_scale[idx] = sc;
        // per-sample min/max candidates (scale >= 0 so min/max commute with mult)
        float lmn = sc * g_xmin[idx];
        float lmx = sc * g_xmax[idx];
#pragma unroll
        for (int o = 16; o > 0; o >>= 1) {
            lmn = fminf(lmn, __shfl_xor_sync(0xFFFFFFFFu, lmn, o));
            lmx = fmaxf(lmx, __shfl_xor_sync(0xFFFFFFFFu, lmx, o));
        }
        const int wid = tid >> 5, lid = tid & 31;
        if (lid == 0) { rmn[wid] = lmn; rmx[wid] = lmx; }
    }
    __syncthreads();
    if (tid == 0) {
        float tn = INFINITY, tx = -INFINITY;
#pragma unroll
        for (int w = 0; w < 8; w++) { tn = fminf(tn, rmn[w]); tx = fmaxf(tx, rmx[w]); }
        g_smin[b] = tn;
        g_smax[b] = tx;
    }
}

// ============ K3: cluster EMA + quant params (1 block, 64 threads) ============
__global__ void __launch_bounds__(64) k3_quant(const float* __restrict__ act_range,
                                               const int*   __restrict__ sc) {
    const int tid = threadIdx.x;
    __shared__ float cs_s[NC], cs_z[NC];
    if (tid < NC) {
        float mn = INFINITY, mx = -INFINITY;
        for (int b = 0; b < B; b++) {
            if (sc[b] == tid) {
                mn = fminf(mn, g_smin[b]);
                mx = fmaxf(mx, g_smax[b]);
            }
        }
        float nmin = act_range[tid*2 + 0] * SMOOTH + mn * (1.0f - SMOOTH);
        float nmax = act_range[tid*2 + 1] * SMOOTH + mx * (1.0f - SMOOTH);
        float s = (nmax - nmin) * (1.0f / Q_MAX);
        float z = -rintf(nmin / s);
        cs_s[tid] = s;
        cs_z[tid] = z;
    }
    __syncthreads();
    {
        const int k = sc[tid];
        float s = cs_s[k];
        g_ss[tid] = s;
        g_zz[tid] = cs_z[k];
        g_is[tid] = 1.0f / s;
    }
}

// ============ K4: elementwise fake-quant, one bc-plane per block ============
// Reverse bc order to hit the x lines K1 left resident in L2.
// Streaming stores so output writes don't evict the x lines we want to reuse.
__device__ __forceinline__ float fq1(float v, float sc, float is_, float z_, float s_) {
    float o = sc * v;
    float q = fminf(fmaxf(rintf(fmaf(o, is_, z_)), 0.f), Q_MAX);
    return (q - z_) * s_;
}

__global__ void __launch_bounds__(256) k4_fq(const float* __restrict__ x,
                                             float* __restrict__ out) {
    const int bc  = (BC - 1) - blockIdx.x;          // reverse order
    const int b   = bc >> 8;
    const int tid = threadIdx.x;
    const float sc = g_scale[bc];
    const float s_ = g_ss[b], z_ = g_zz[b], is_ = g_is[b];

    const float4* xb = reinterpret_cast<const float4*>(x) + (size_t)bc * (HW/4);
    float4*       ob = reinterpret_cast<float4*>(out)      + (size_t)bc * (HW/4);

    float4 v0 = __ldcs(&xb[tid]);
    float4 v1 = __ldcs(&xb[tid + 256]);
    float4 v2 = __ldcs(&xb[tid + 512]);
    float4 v3 = __ldcs(&xb[tid + 768]);

    float4 r;
    r.x = fq1(v0.x, sc, is_, z_, s_); r.y = fq1(v0.y, sc, is_, z_, s_);
    r.z = fq1(v0.z, sc, is_, z_, s_); r.w = fq1(v0.w, sc, is_, z_, s_);
    __stcs(&ob[tid], r);
    r.x = fq1(v1.x, sc, is_, z_, s_); r.y = fq1(v1.y, sc, is_, z_, s_);
    r.z = fq1(v1.z, sc, is_, z_, s_); r.w = fq1(v1.w, sc, is_, z_, s_);
    __stcs(&ob[tid + 256], r);
    r.x = fq1(v2.x, sc, is_, z_, s_); r.y = fq1(v2.y, sc, is_, z_, s_);
    r.z = fq1(v2.z, sc, is_, z_, s_); r.w = fq1(v2.w, sc, is_, z_, s_);
    __stcs(&ob[tid + 512], r);
    r.x = fq1(v3.x, sc, is_, z_, s_); r.y = fq1(v3.y, sc, is_, z_, s_);
    r.z = fq1(v3.z, sc, is_, z_, s_); r.w = fq1(v3.w, sc, is_, z_, s_);
    __stcs(&ob[tid + 768], r);
}

extern "C" void kernel_launch(void* const* d_in, const int* in_sizes, int n_in,
                              void* d_out, int out_size) {
    const float* x   = (const float*)d_in[0];
    const float* w1  = (const float*)d_in[1];
    const float* b1  = (const float*)d_in[2];
    const float* w2  = (const float*)d_in[3];
    const float* b2  = (const float*)d_in[4];
    const float* ar  = (const float*)d_in[5];
    const int*   sc  = (const int*)  d_in[6];
    float* out = (float*)d_out;

    k1_stats<<<BC, 256>>>(x);
    k2_se<<<B, 256>>>(w1, b1, w2, b2);
    k3_quant<<<1, 64>>>(ar, sc);
    k4_fq<<<BC, 256>>>(x, out);
}

// round 7
// speedup vs baseline: 1.3734x; 1.0963x over previous
#include <cuda_runtime.h>
#include <math.h>

#define B   64
#define C   256
#define HW  4096
#define CS  64
#define NC  8
#define BC  (B*C)          // 16384
#define Q_MAX 255.0f
#define SMOOTH 0.995f
// planes [SPLIT, BC) get pinned in L2 by K1 (evict_last); 6144 planes = 96 MB
#define SPLIT 10240

// ---- scratch (no allocations allowed) ----
__device__ float g_pooled[BC];
__device__ float g_xmin[BC];
__device__ float g_xmax[BC];
__device__ float g_scale[BC];
__device__ float g_smin[B];
__device__ float g_smax[B];
__device__ float g_ss[B];
__device__ float g_zz[B];
__device__ float g_is[B];

__device__ __forceinline__ unsigned long long mk_evict_last_policy() {
    unsigned long long pol;
    asm volatile("createpolicy.fractional.L2::evict_last.b64 %0, 1.0;" : "=l"(pol));
    return pol;
}
__device__ __forceinline__ float4 ld_evict_last(const float4* p, unsigned long long pol) {
    float4 v;
    asm volatile("ld.global.L2::cache_hint.v4.f32 {%0,%1,%2,%3}, [%4], %5;"
                 : "=f"(v.x), "=f"(v.y), "=f"(v.z), "=f"(v.w) : "l"(p), "l"(pol));
    return v;
}
__device__ __forceinline__ float4 ld_stream(const float4* p) {
    float4 v;
    asm volatile("ld.global.cs.v4.f32 {%0,%1,%2,%3}, [%4];"
                 : "=f"(v.x), "=f"(v.y), "=f"(v.z), "=f"(v.w) : "l"(p));
    return v;
}

// ============ K1: per-(b,c) sum / min / max over HW=4096 ============
// Head planes: streaming loads. Tail planes: evict_last (pin in L2 for K4).
__global__ void __launch_bounds__(256) k1_stats(const float* __restrict__ x) {
    const int bc  = blockIdx.x;             // 0..16383
    const int tid = threadIdx.x;
    const float4* xb = reinterpret_cast<const float4*>(x) + (size_t)bc * (HW/4);

    float4 v0, v1, v2, v3;
    if (bc >= SPLIT) {
        const unsigned long long pol = mk_evict_last_policy();
        v0 = ld_evict_last(&xb[tid],       pol);
        v1 = ld_evict_last(&xb[tid + 256], pol);
        v2 = ld_evict_last(&xb[tid + 512], pol);
        v3 = ld_evict_last(&xb[tid + 768], pol);
    } else {
        v0 = ld_stream(&xb[tid]);
        v1 = ld_stream(&xb[tid + 256]);
        v2 = ld_stream(&xb[tid + 512]);
        v3 = ld_stream(&xb[tid + 768]);
    }

    float sum = ((v0.x + v0.y) + (v0.z + v0.w)) + ((v1.x + v1.y) + (v1.z + v1.w))
              + ((v2.x + v2.y) + (v2.z + v2.w)) + ((v3.x + v3.y) + (v3.z + v3.w));
    float mn = fminf(fminf(fminf(fminf(v0.x, v0.y), fminf(v0.z, v0.w)),
                           fminf(fminf(v1.x, v1.y), fminf(v1.z, v1.w))),
                     fminf(fminf(fminf(v2.x, v2.y), fminf(v2.z, v2.w)),
                           fminf(fminf(v3.x, v3.y), fminf(v3.z, v3.w))));
    float mx = fmaxf(fmaxf(fmaxf(fmaxf(v0.x, v0.y), fmaxf(v0.z, v0.w)),
                           fmaxf(fmaxf(v1.x, v1.y), fmaxf(v1.z, v1.w))),
                     fmaxf(fmaxf(fmaxf(v2.x, v2.y), fmaxf(v2.z, v2.w)),
                           fmaxf(fmaxf(v3.x, v3.y), fmaxf(v3.z, v3.w))));
#pragma unroll
    for (int o = 16; o > 0; o >>= 1) {
        sum += __shfl_xor_sync(0xFFFFFFFFu, sum, o);
        mn = fminf(mn, __shfl_xor_sync(0xFFFFFFFFu, mn, o));
        mx = fmaxf(mx, __shfl_xor_sync(0xFFFFFFFFu, mx, o));
    }
    __shared__ float ssum[8], smn[8], smx[8];
    const int wid = tid >> 5, lid = tid & 31;
    if (lid == 0) { ssum[wid] = sum; smn[wid] = mn; smx[wid] = mx; }
    __syncthreads();
    if (tid == 0) {
        float ts = 0.f, tn = INFINITY, tx = -INFINITY;
#pragma unroll
        for (int w = 0; w < 8; w++) {
            ts += ssum[w]; tn = fminf(tn, smn[w]); tx = fmaxf(tx, smx[w]);
        }
        g_pooled[bc] = ts * (1.0f / HW);
        g_xmin[bc] = tn;
        g_xmax[bc] = tx;
    }
}

// ============ K2: SE MLP per sample b (one block/sample) ============
// GEMM1 split 4-ways per output s (64-FMA chains + shfl combine).
__global__ void __launch_bounds__(256) k2_se(const float* __restrict__ w1,
                                             const float* __restrict__ b1,
                                             const float* __restrict__ w2,
                                             const float* __restrict__ b2) {
    const int b = blockIdx.x;
    const int tid = threadIdx.x;
    __shared__ float sp[C];     // pooled[b, :]
    __shared__ float sh[CS];    // hidden
    __shared__ float rmn[8], rmx[8];

    sp[tid] = g_pooled[b*C + tid];
    __syncthreads();

    // GEMM1: s = tid>>2, 4 partial sums over 64 channels each
    {
        const int s    = tid >> 2;
        const int part = tid & 3;
        const float* wr = w1 + s * C + part * 64;
        const float* pp = sp + part * 64;
        float a0 = 0.f, a1 = 0.f, a2 = 0.f, a3 = 0.f;
#pragma unroll
        for (int c = 0; c < 64; c += 4) {
            a0 = fmaf(pp[c+0], wr[c+0], a0);
            a1 = fmaf(pp[c+1], wr[c+1], a1);
            a2 = fmaf(pp[c+2], wr[c+2], a2);
            a3 = fmaf(pp[c+3], wr[c+3], a3);
        }
        float acc = (a0 + a1) + (a2 + a3);
        acc += __shfl_xor_sync(0xFFFFFFFFu, acc, 1);
        acc += __shfl_xor_sync(0xFFFFFFFFu, acc, 2);
        if (part == 0) sh[s] = fmaxf(acc + b1[s], 0.f);   // relu
    }
    __syncthreads();

    // GEMM2 + hardsigmoid + per-sample min/max candidates; c = tid
    {
        float a0 = 0.f, a1 = 0.f, a2 = 0.f, a3 = 0.f;
        const float* wr = w2 + tid * CS;
#pragma unroll
        for (int s = 0; s < CS; s += 4) {
            a0 = fmaf(sh[s+0], wr[s+0], a0);
            a1 = fmaf(sh[s+1], wr[s+1], a1);
            a2 = fmaf(sh[s+2], wr[s+2], a2);
            a3 = fmaf(sh[s+3], wr[s+3], a3);
        }
        float acc = ((a0 + a1) + (a2 + a3)) + b2[tid];
        float sc = fminf(fmaxf(acc * (1.0f/6.0f) + 0.5f, 0.f), 1.f);  // hardsigmoid
        const int idx = b*C + tid;
        g_scale[idx] = sc;
        // scale >= 0, so min/max commute with the multiply
        float lmn = sc * g_xmin[idx];
        float lmx = sc * g_xmax[idx];
#pragma unroll
        for (int o = 16; o > 0; o >>= 1) {
            lmn = fminf(lmn, __shfl_xor_sync(0xFFFFFFFFu, lmn, o));
            lmx = fmaxf(lmx, __shfl_xor_sync(0xFFFFFFFFu, lmx, o));
        }
        const int wid = tid >> 5, lid = tid & 31;
        if (lid == 0) { rmn[wid] = lmn; rmx[wid] = lmx; }
    }
    __syncthreads();
    if (tid == 0) {
        float tn = INFINITY, tx = -INFINITY;
#pragma unroll
        for (int w = 0; w < 8; w++) { tn = fminf(tn, rmn[w]); tx = fmaxf(tx, rmx[w]); }
        g_smin[b] = tn;
        g_smax[b] = tx;
    }
}

// ============ K3: cluster EMA + quant params (1 block, 64 threads) ============
__global__ void __launch_bounds__(64) k3_quant(const float* __restrict__ act_range,
                                               const int*   __restrict__ sc) {
    const int tid = threadIdx.x;
    __shared__ float smn_s[B], smx_s[B];
    __shared__ int   scid[B];
    __shared__ float cs_s[NC], cs_z[NC];

    smn_s[tid] = g_smin[tid];
    smx_s[tid] = g_smax[tid];
    scid[tid]  = sc[tid];
    __syncthreads();

    if (tid < NC) {
        float mn = INFINITY, mx = -INFINITY;
#pragma unroll 8
        for (int b = 0; b < B; b++) {
            if (scid[b] == tid) {
                mn = fminf(mn, smn_s[b]);
                mx = fmaxf(mx, smx_s[b]);
            }
        }
        float nmin = act_range[tid*2 + 0] * SMOOTH + mn * (1.0f - SMOOTH);
        float nmax = act_range[tid*2 + 1] * SMOOTH + mx * (1.0f - SMOOTH);
        float s = (nmax - nmin) * (1.0f / Q_MAX);
        float z = -rintf(nmin / s);
        cs_s[tid] = s;
        cs_z[tid] = z;
    }
    __syncthreads();
    {
        const int k = scid[tid];
        float s = cs_s[k];
        g_ss[tid] = s;
        g_zz[tid] = cs_z[k];
        g_is[tid] = 1.0f / s;
    }
}

// ============ K4: elementwise fake-quant, one bc-plane per block ============
// Reverse bc order: first blocks read the planes K1 pinned with evict_last.
__device__ __forceinline__ float fq1(float v, float sc, float is_, float z_, float s_) {
    float o = sc * v;
    float q = fminf(fmaxf(rintf(fmaf(o, is_, z_)), 0.f), Q_MAX);
    return (q - z_) * s_;
}

__global__ void __launch_bounds__(256) k4_fq(const float* __restrict__ x,
                                             float* __restrict__ out) {
    const int bc  = (BC - 1) - blockIdx.x;          // reverse order
    const int b   = bc >> 8;
    const int tid = threadIdx.x;
    const float sc = g_scale[bc];
    const float s_ = g_ss[b], z_ = g_zz[b], is_ = g_is[b];

    const float4* xb = reinterpret_cast<const float4*>(x) + (size_t)bc * (HW/4);
    float4*       ob = reinterpret_cast<float4*>(out)      + (size_t)bc * (HW/4);

    float4 v0 = ld_stream(&xb[tid]);
    float4 v1 = ld_stream(&xb[tid + 256]);
    float4 v2 = ld_stream(&xb[tid + 512]);
    float4 v3 = ld_stream(&xb[tid + 768]);

    float4 r;
    r.x = fq1(v0.x, sc, is_, z_, s_); r.y = fq1(v0.y, sc, is_, z_, s_);
    r.z = fq1(v0.z, sc, is_, z_, s_); r.w = fq1(v0.w, sc, is_, z_, s_);
    __stcs(&ob[tid], r);
    r.x = fq1(v1.x, sc, is_, z_, s_); r.y = fq1(v1.y, sc, is_, z_, s_);
    r.z = fq1(v1.z, sc, is_, z_, s_); r.w = fq1(v1.w, sc, is_, z_, s_);
    __stcs(&ob[tid + 256], r);
    r.x = fq1(v2.x, sc, is_, z_, s_); r.y = fq1(v2.y, sc, is_, z_, s_);
    r.z = fq1(v2.z, sc, is_, z_, s_); r.w = fq1(v2.w, sc, is_, z_, s_);
    __stcs(&ob[tid + 512], r);
    r.x = fq1(v3.x, sc, is_, z_, s_); r.y = fq1(v3.y, sc, is_, z_, s_);
    r.z = fq1(v3.z, sc, is_, z_, s_); r.w = fq1(v3.w, sc, is_, z_, s_);
    __stcs(&ob[tid + 768], r);
}

extern "C" void kernel_launch(void* const* d_in, const int* in_sizes, int n_in,
                              void* d_out, int out_size) {
    const float* x   = (const float*)d_in[0];
    const float* w1  = (const float*)d_in[1];
    const float* b1  = (const float*)d_in[2];
    const float* w2  = (const float*)d_in[3];
    const float* b2  = (const float*)d_in[4];
    const float* ar  = (const float*)d_in[5];
    const int*   sc  = (const int*)  d_in[6];
    float* out = (float*)d_out;

    k1_stats<<<BC, 256>>>(x);
    k2_se<<<B, 256>>>(w1, b1, w2, b2);
    k3_quant<<<1, 64>>>(ar, sc);
    k4_fq<<<BC, 256>>>(x, out);
}